// round 1
// baseline (speedup 1.0000x reference)
#include <cuda_runtime.h>

#define BATCH 256
#define INF   1024
#define OUTF  128
#define KD    8
#define NCOLS (OUTF * KD)     // 1024, columns of M
#define OUTW  (INF + OUTF)    // 1152, output row width

// Scratch for M = x @ T  (256 x 1024 f32 = 1 MB). Device global: no allocs allowed.
__device__ float g_M[BATCH * NCOLS];

// ---------------------------------------------------------------------------
// Kernel 1: SGEMM  C(256x1024) = A(256x1024) @ B(1024x1024)
// Tile: BM=32, BN=64, BK=16; 256 threads; each thread computes 2x4.
// Grid: (1024/64, 256/32) = (16, 8) = 128 blocks.
// ---------------------------------------------------------------------------
#define BM 32
#define BN 64
#define BK 16

__global__ __launch_bounds__(256) void gemm_kernel(
    const float* __restrict__ A, const float* __restrict__ B, float* __restrict__ C)
{
    __shared__ float  As[BK][BM];        // transposed A tile
    __shared__ float4 Bs[BK][BN / 4];    // B tile, float4 rows

    const int tid = threadIdx.x;
    const int bn  = blockIdx.x;          // 0..15  (column tile)
    const int bm  = blockIdx.y;          // 0..7   (row tile)
    const int ty  = tid >> 4;            // 0..15 -> row pair
    const int tx  = tid & 15;            // 0..15 -> col quad

    float acc[2][4] = {};

    for (int k0 = 0; k0 < INF; k0 += BK) {
        // Load A tile: 32x16 = 512 floats, float2 per thread.
        {
            const int r  = tid >> 3;         // 0..31
            const int kk = (tid & 7) * 2;    // 0,2,...,14
            const float2 v = *reinterpret_cast<const float2*>(
                &A[(bm * BM + r) * INF + k0 + kk]);
            As[kk][r]     = v.x;
            As[kk + 1][r] = v.y;
        }
        // Load B tile: 16x64 = 1024 floats, float4 per thread (fully coalesced).
        {
            const int r  = tid >> 4;         // 0..15
            const int c4 = tid & 15;         // 0..15
            Bs[r][c4] = *reinterpret_cast<const float4*>(
                &B[(k0 + r) * NCOLS + bn * BN + c4 * 4]);
        }
        __syncthreads();

        #pragma unroll
        for (int kk = 0; kk < BK; kk++) {
            const float a0 = As[kk][ty * 2];
            const float a1 = As[kk][ty * 2 + 1];
            const float4 b = Bs[kk][tx];
            acc[0][0] += a0 * b.x;  acc[0][1] += a0 * b.y;
            acc[0][2] += a0 * b.z;  acc[0][3] += a0 * b.w;
            acc[1][0] += a1 * b.x;  acc[1][1] += a1 * b.y;
            acc[1][2] += a1 * b.z;  acc[1][3] += a1 * b.w;
        }
        __syncthreads();
    }

    const int row = bm * BM + ty * 2;
    const int col = bn * BN + tx * 4;
    #pragma unroll
    for (int i = 0; i < 2; i++) {
        float4 v = make_float4(acc[i][0], acc[i][1], acc[i][2], acc[i][3]);
        *reinterpret_cast<float4*>(&C[(row + i) * NCOLS + col]) = v;
    }
}

// ---------------------------------------------------------------------------
// Kernel 2: pairwise L1 + exp-sum.
// One block per output feature o (128 blocks), 256 threads (one per sample i).
// Stage M[:, o, :] (256 x 8 f32 = 8 KB) in shared; own row in registers.
// c[i,o] = sum_j exp(-sum_k |M[i,o,k]-M[j,o,k]|) - 1   (self term included then
// subtracted, mirroring the reference's cancellation).
// ---------------------------------------------------------------------------
__global__ __launch_bounds__(256) void pairwise_kernel(
    const float* __restrict__ M, float* __restrict__ out)
{
    const int o = blockIdx.x;    // 0..127
    const int i = threadIdx.x;   // 0..255

    __shared__ float4 Ms[BATCH][2];

    const float4 a0 = *reinterpret_cast<const float4*>(&M[i * NCOLS + o * KD]);
    const float4 a1 = *reinterpret_cast<const float4*>(&M[i * NCOLS + o * KD + 4]);
    Ms[i][0] = a0;
    Ms[i][1] = a1;
    __syncthreads();

    float s = 0.0f;
    #pragma unroll 4
    for (int j = 0; j < BATCH; j++) {
        const float4 b0 = Ms[j][0];   // uniform j -> broadcast, conflict-free
        const float4 b1 = Ms[j][1];
        float d = fabsf(a0.x - b0.x) + fabsf(a0.y - b0.y)
                + fabsf(a0.z - b0.z) + fabsf(a0.w - b0.w)
                + fabsf(a1.x - b1.x) + fabsf(a1.y - b1.y)
                + fabsf(a1.z - b1.z) + fabsf(a1.w - b1.w);
        s += __expf(-d);
    }
    out[i * OUTW + INF + o] = s - 1.0f;
}

// ---------------------------------------------------------------------------
// Kernel 3: copy x into out[:, 0:1024] (strided rows of width 1152).
// ---------------------------------------------------------------------------
__global__ __launch_bounds__(256) void copy_x_kernel(
    const float* __restrict__ x, float* __restrict__ out)
{
    const int idx = blockIdx.x * blockDim.x + threadIdx.x;   // float4 index
    const int total = BATCH * (INF / 4);                     // 65536
    if (idx < total) {
        const int row = idx / (INF / 4);
        const int c4  = idx % (INF / 4);
        const float4 v = reinterpret_cast<const float4*>(x)[idx];
        *reinterpret_cast<float4*>(&out[row * OUTW + c4 * 4]) = v;
    }
}

// ---------------------------------------------------------------------------
extern "C" void kernel_launch(void* const* d_in, const int* in_sizes, int n_in,
                              void* d_out, int out_size)
{
    const float* x = (const float*)d_in[0];   // (256, 1024)
    const float* T = (const float*)d_in[1];   // (1024, 128, 8) == (1024, 1024)
    float* out = (float*)d_out;               // (256, 1152)

    float* M;
    cudaGetSymbolAddress((void**)&M, g_M);

    dim3 ggrid(NCOLS / BN, BATCH / BM);       // (16, 8)
    gemm_kernel<<<ggrid, 256>>>(x, T, M);

    pairwise_kernel<<<OUTF, 256>>>(M, out);

    copy_x_kernel<<<(BATCH * (INF / 4) + 255) / 256, 256>>>(x, out);
}

// round 3
// speedup vs baseline: 1.2556x; 1.2556x over previous
#include <cuda_runtime.h>
#include <cuda_bf16.h>
#include <cstdint>

#define BATCH 256
#define INF   1024
#define OUTF  128
#define KD    8
#define NCOLS (OUTF * KD)     // 1024
#define OUTW  (INF + OUTF)    // 1152

// Device scratch (no allocs allowed)
__device__ float         g_M[BATCH * NCOLS];     // M = x @ T (fp32)
__device__ __nv_bfloat16 g_Abf[BATCH * INF];     // x in bf16, row-major (K-major)
__device__ __nv_bfloat16 g_Bt[NCOLS * INF];      // T transposed: Bt[n][k] (B col-major)

__device__ __forceinline__ uint32_t smem_u32(const void* p) {
    uint32_t a;
    asm("{ .reg .u64 t; cvta.to.shared.u64 t, %1; cvt.u32.u64 %0, t; }" : "=r"(a) : "l"(p));
    return a;
}
#define SWZ128(b) ((b) ^ (((b) >> 3) & 0x70))

// ---------------------------------------------------------------------------
// Prep A: x fp32 -> bf16
// ---------------------------------------------------------------------------
__global__ __launch_bounds__(256) void convert_x_kernel(
    const float* __restrict__ x, __nv_bfloat16* __restrict__ xb)
{
    const int idx = blockIdx.x * blockDim.x + threadIdx.x;   // float4 index
    if (idx < BATCH * INF / 4) {
        const float4 v = reinterpret_cast<const float4*>(x)[idx];
        reinterpret_cast<__nv_bfloat162*>(xb)[idx * 2]     = __floats2bfloat162_rn(v.x, v.y);
        reinterpret_cast<__nv_bfloat162*>(xb)[idx * 2 + 1] = __floats2bfloat162_rn(v.z, v.w);
    }
}

// ---------------------------------------------------------------------------
// Prep B: T[k][n] fp32 -> Bt[n][k] bf16 (tiled transpose)
// ---------------------------------------------------------------------------
__global__ __launch_bounds__(256) void transpose_T_kernel(
    const float* __restrict__ T, __nv_bfloat16* __restrict__ Bt)
{
    __shared__ float tile[32][33];
    const int tx = threadIdx.x;  // 0..31
    const int ty = threadIdx.y;  // 0..7
    const int n = blockIdx.x * 32 + tx;
    #pragma unroll
    for (int r = 0; r < 4; r++) {
        const int k = blockIdx.y * 32 + ty + r * 8;
        tile[ty + r * 8][tx] = T[k * NCOLS + n];
    }
    __syncthreads();
    const int k_out = blockIdx.y * 32 + tx;
    #pragma unroll
    for (int r = 0; r < 4; r++) {
        const int n_out = blockIdx.x * 32 + ty + r * 8;
        Bt[n_out * INF + k_out] = __float2bfloat16(tile[tx][ty + r * 8]);
    }
}

// ---------------------------------------------------------------------------
// HMMA GEMM via mma.sync.m16n8k16 bf16 -> f32.
// C(256x1024) = A(256x1024) @ Bt(1024x1024)^T
// CTA tile 64x64, BK=64 (16 chunks). 8 warps = 2(m) x 4(n); warp tile 32x16.
// smem tiles 64 rows x 128B, SW128 swizzled -> conflict-free ldmatrix.
// Grid: (16 nt, 4 mt) = 64 CTAs.
// ---------------------------------------------------------------------------
__global__ __launch_bounds__(256) void gemm_mma_kernel(
    const __nv_bfloat16* __restrict__ A, const __nv_bfloat16* __restrict__ B,
    float* __restrict__ C)
{
    __shared__ __align__(1024) char sAc[64 * 128];
    __shared__ __align__(1024) char sBc[64 * 128];

    const int tid = threadIdx.x;
    const int wid = tid >> 5;
    const int lid = tid & 31;
    const int nt = blockIdx.x;   // 0..15
    const int mt = blockIdx.y;   // 0..3
    const int w_m = wid >> 2;    // 0..1
    const int w_n = wid & 3;     // 0..3

    const uint32_t sA = smem_u32(sAc);
    const uint32_t sB = smem_u32(sBc);

    const __nv_bfloat16* Ag = A + (size_t)(mt * 64) * INF;
    const __nv_bfloat16* Bg = B + (size_t)(nt * 64) * INF;

    float c[2][2][4];
    #pragma unroll
    for (int i = 0; i < 2; i++)
        #pragma unroll
        for (int j = 0; j < 2; j++)
            #pragma unroll
            for (int q = 0; q < 4; q++) c[i][j][q] = 0.0f;

    // Precompute lane parts of ldmatrix addresses (row/chunk offsets).
    const int l7   = lid & 7;
    const int lb3  = (lid >> 3) & 1;
    const int lb4  = (lid >> 4) & 1;
    // A: row = mb + l7 + lb3*8 ; kchunk += lb4
    // B: row = nb + l7 + lb4*8 ; kchunk += lb3
    const int a_row_lane = l7 + lb3 * 8;
    const int b_row_lane = l7 + lb4 * 8;
    const int nb = w_n * 16;

    for (int ch = 0; ch < 16; ch++) {
        const int k0 = ch * 64;
        // Load A and B tiles: 512 x 16B units each, 2 per thread.
        #pragma unroll
        for (int it = 0; it < 2; it++) {
            const int u   = tid + it * 256;     // 0..511
            const int row = u >> 3;
            const int kc  = u & 7;
            const uint32_t soff = SWZ128((uint32_t)(row * 128 + kc * 16));
            *reinterpret_cast<uint4*>(sAc + soff) =
                *reinterpret_cast<const uint4*>(Ag + row * INF + k0 + kc * 8);
            *reinterpret_cast<uint4*>(sBc + soff) =
                *reinterpret_cast<const uint4*>(Bg + row * INF + k0 + kc * 8);
        }
        __syncthreads();

        #pragma unroll
        for (int s = 0; s < 4; s++) {
            // B fragments for both n-subtiles: 16(k) x 16(n) via ldmatrix.x4
            uint32_t b0, b1, b2, b3;
            {
                const uint32_t boff = SWZ128(
                    (uint32_t)((nb + b_row_lane) * 128 + (s * 2 + lb3) * 16));
                asm volatile(
                    "ldmatrix.sync.aligned.m8n8.x4.shared.b16 {%0,%1,%2,%3}, [%4];"
                    : "=r"(b0), "=r"(b1), "=r"(b2), "=r"(b3) : "r"(sB + boff));
            }
            #pragma unroll
            for (int mf = 0; mf < 2; mf++) {
                const int mb = w_m * 32 + mf * 16;
                uint32_t a0, a1, a2, a3;
                const uint32_t aoff = SWZ128(
                    (uint32_t)((mb + a_row_lane) * 128 + (s * 2 + lb4) * 16));
                asm volatile(
                    "ldmatrix.sync.aligned.m8n8.x4.shared.b16 {%0,%1,%2,%3}, [%4];"
                    : "=r"(a0), "=r"(a1), "=r"(a2), "=r"(a3) : "r"(sA + aoff));
                asm volatile(
                    "mma.sync.aligned.m16n8k16.row.col.f32.bf16.bf16.f32 "
                    "{%0,%1,%2,%3}, {%4,%5,%6,%7}, {%8,%9}, {%0,%1,%2,%3};"
                    : "+f"(c[mf][0][0]), "+f"(c[mf][0][1]),
                      "+f"(c[mf][0][2]), "+f"(c[mf][0][3])
                    : "r"(a0), "r"(a1), "r"(a2), "r"(a3), "r"(b0), "r"(b1));
                asm volatile(
                    "mma.sync.aligned.m16n8k16.row.col.f32.bf16.bf16.f32 "
                    "{%0,%1,%2,%3}, {%4,%5,%6,%7}, {%8,%9}, {%0,%1,%2,%3};"
                    : "+f"(c[mf][1][0]), "+f"(c[mf][1][1]),
                      "+f"(c[mf][1][2]), "+f"(c[mf][1][3])
                    : "r"(a0), "r"(a1), "r"(a2), "r"(a3), "r"(b2), "r"(b3));
            }
        }
        __syncthreads();
    }

    // Epilogue: fragment (g = lid>>2, tig = lid&3)
    const int g = lid >> 2;
    const int tig = lid & 3;
    #pragma unroll
    for (int mf = 0; mf < 2; mf++) {
        const int row = mt * 64 + w_m * 32 + mf * 16 + g;
        #pragma unroll
        for (int nf = 0; nf < 2; nf++) {
            const int col = nt * 64 + w_n * 16 + nf * 8 + tig * 2;
            *reinterpret_cast<float2*>(&C[row * NCOLS + col]) =
                make_float2(c[mf][nf][0], c[mf][nf][1]);
            *reinterpret_cast<float2*>(&C[(row + 8) * NCOLS + col]) =
                make_float2(c[mf][nf][2], c[mf][nf][3]);
        }
    }
}

// ---------------------------------------------------------------------------
// Pairwise L1 + exp-sum: one block per feature o, one thread per sample i.
// ---------------------------------------------------------------------------
__global__ __launch_bounds__(256) void pairwise_kernel(
    const float* __restrict__ M, float* __restrict__ out)
{
    const int o = blockIdx.x;    // 0..127
    const int i = threadIdx.x;   // 0..255

    __shared__ float4 Ms[BATCH][2];

    const float4 a0 = *reinterpret_cast<const float4*>(&M[i * NCOLS + o * KD]);
    const float4 a1 = *reinterpret_cast<const float4*>(&M[i * NCOLS + o * KD + 4]);
    Ms[i][0] = a0;
    Ms[i][1] = a1;
    __syncthreads();

    float s = 0.0f;
    #pragma unroll 4
    for (int j = 0; j < BATCH; j++) {
        const float4 b0 = Ms[j][0];
        const float4 b1 = Ms[j][1];
        float d = fabsf(a0.x - b0.x) + fabsf(a0.y - b0.y)
                + fabsf(a0.z - b0.z) + fabsf(a0.w - b0.w)
                + fabsf(a1.x - b1.x) + fabsf(a1.y - b1.y)
                + fabsf(a1.z - b1.z) + fabsf(a1.w - b1.w);
        s += __expf(-d);
    }
    out[i * OUTW + INF + o] = s - 1.0f;
}

// ---------------------------------------------------------------------------
// Copy x into out[:, 0:1024]
// ---------------------------------------------------------------------------
__global__ __launch_bounds__(256) void copy_x_kernel(
    const float* __restrict__ x, float* __restrict__ out)
{
    const int idx = blockIdx.x * blockDim.x + threadIdx.x;
    const int total = BATCH * (INF / 4);
    if (idx < total) {
        const int row = idx / (INF / 4);
        const int c4  = idx % (INF / 4);
        const float4 v = reinterpret_cast<const float4*>(x)[idx];
        *reinterpret_cast<float4*>(&out[row * OUTW + c4 * 4]) = v;
    }
}

// ---------------------------------------------------------------------------
extern "C" void kernel_launch(void* const* d_in, const int* in_sizes, int n_in,
                              void* d_out, int out_size)
{
    const float* x = (const float*)d_in[0];   // (256, 1024)
    const float* T = (const float*)d_in[1];   // (1024, 1024)
    float* out = (float*)d_out;               // (256, 1152)

    float* M;
    __nv_bfloat16 *Abf, *Bt;
    cudaGetSymbolAddress((void**)&M, g_M);
    cudaGetSymbolAddress((void**)&Abf, g_Abf);
    cudaGetSymbolAddress((void**)&Bt, g_Bt);

    copy_x_kernel<<<(BATCH * (INF / 4) + 255) / 256, 256>>>(x, out);
    convert_x_kernel<<<(BATCH * INF / 4 + 255) / 256, 256>>>(x, Abf);
    transpose_T_kernel<<<dim3(NCOLS / 32, INF / 32), dim3(32, 8)>>>(T, Bt);

    gemm_mma_kernel<<<dim3(NCOLS / 64, BATCH / 64), 256>>>(Abf, Bt, M);

    pairwise_kernel<<<OUTF, 256>>>(M, out);
}

// round 4
// speedup vs baseline: 2.3658x; 1.8842x over previous
#include <cuda_runtime.h>
#include <cuda_bf16.h>
#include <cstdint>

#define BATCH 256
#define INF   1024
#define OUTF  128
#define KD    8
#define NCOLS (OUTF * KD)     // 1024
#define OUTW  (INF + OUTF)    // 1152

// Device scratch (no allocs allowed)
__device__ float         g_M[BATCH * NCOLS];     // M = x @ T (fp32)
__device__ __nv_bfloat16 g_Abf[BATCH * INF];     // x in bf16 (K-major)
__device__ __nv_bfloat16 g_Bt[NCOLS * INF];      // T transposed: Bt[n][k]

__device__ __forceinline__ uint32_t smem_u32(const void* p) {
    uint32_t a;
    asm("{ .reg .u64 t; cvta.to.shared.u64 t, %1; cvt.u32.u64 %0, t; }" : "=r"(a) : "l"(p));
    return a;
}
#define SWZ128(b) ((b) ^ (((b) >> 3) & 0x70))
#define CP_ASYNC16(saddr, gptr) \
    asm volatile("cp.async.cg.shared.global [%0], [%1], 16;" :: "r"(saddr), "l"(gptr) : "memory")
#define CP_COMMIT() asm volatile("cp.async.commit_group;" ::: "memory")
#define CP_WAIT1()  asm volatile("cp.async.wait_group 1;" ::: "memory")

// ---------------------------------------------------------------------------
// Fused prep: copy x into out[:, :1024] AND convert x -> bf16 (one read).
// ---------------------------------------------------------------------------
__global__ __launch_bounds__(256) void prep_x_kernel(
    const float* __restrict__ x, float* __restrict__ out,
    __nv_bfloat16* __restrict__ xb)
{
    const int idx = blockIdx.x * blockDim.x + threadIdx.x;   // float4 index
    if (idx < BATCH * INF / 4) {
        const float4 v = reinterpret_cast<const float4*>(x)[idx];
        const int row = idx >> 8;              // / (1024/4)
        const int c4  = idx & 255;
        *reinterpret_cast<float4*>(&out[row * OUTW + c4 * 4]) = v;
        reinterpret_cast<__nv_bfloat162*>(xb)[idx * 2]     = __floats2bfloat162_rn(v.x, v.y);
        reinterpret_cast<__nv_bfloat162*>(xb)[idx * 2 + 1] = __floats2bfloat162_rn(v.z, v.w);
    }
}

// ---------------------------------------------------------------------------
// Prep B: T[k][n] fp32 -> Bt[n][k] bf16 (tiled transpose)
// ---------------------------------------------------------------------------
__global__ __launch_bounds__(256) void transpose_T_kernel(
    const float* __restrict__ T, __nv_bfloat16* __restrict__ Bt)
{
    __shared__ float tile[32][33];
    const int tx = threadIdx.x;  // 0..31
    const int ty = threadIdx.y;  // 0..7
    const int n = blockIdx.x * 32 + tx;
    #pragma unroll
    for (int r = 0; r < 4; r++) {
        const int k = blockIdx.y * 32 + ty + r * 8;
        tile[ty + r * 8][tx] = T[k * NCOLS + n];
    }
    __syncthreads();
    const int k_out = blockIdx.y * 32 + tx;
    #pragma unroll
    for (int r = 0; r < 4; r++) {
        const int n_out = blockIdx.x * 32 + ty + r * 8;
        Bt[n_out * INF + k_out] = __float2bfloat16(tile[tx][ty + r * 8]);
    }
}

// ---------------------------------------------------------------------------
// HMMA GEMM, 3-stage cp.async pipeline.
// C(256x1024) = A(256x1024) @ Bt(1024x1024)^T
// CTA tile 64x64, BK=64 (16 chunks). 8 warps = 2(m) x 4(n); warp tile 32x16.
// smem: 3 stages x (A 8KB + B 8KB) = 48KB dynamic, SW128 swizzled.
// Grid: (16 nt, 4 mt) = 64 CTAs.
// ---------------------------------------------------------------------------
#define STAGE_BYTES 16384
#define GEMM_SMEM   (3 * STAGE_BYTES)

__global__ __launch_bounds__(256) void gemm_mma_kernel(
    const __nv_bfloat16* __restrict__ A, const __nv_bfloat16* __restrict__ B,
    float* __restrict__ C)
{
    extern __shared__ __align__(1024) char dsm[];

    const int tid = threadIdx.x;
    const int wid = tid >> 5;
    const int lid = tid & 31;
    const int nt = blockIdx.x;   // 0..15
    const int mt = blockIdx.y;   // 0..3
    const int w_m = wid >> 2;    // 0..1
    const int w_n = wid & 3;     // 0..3

    const uint32_t sbase = smem_u32(dsm);

    const __nv_bfloat16* Ag = A + (size_t)(mt * 64) * INF;
    const __nv_bfloat16* Bg = B + (size_t)(nt * 64) * INF;

    // Per-thread load coordinates (2 units per operand per stage).
    const int ld_row  = tid >> 3;          // 0..31  (then +32 for second unit)
    const int ld_kc   = tid & 7;           // 0..7
    const uint32_t soffA0 = SWZ128((uint32_t)(ld_row * 128 + ld_kc * 16));
    const uint32_t soffA1 = SWZ128((uint32_t)((ld_row + 32) * 128 + ld_kc * 16));

    float c[2][2][4];
    #pragma unroll
    for (int i = 0; i < 2; i++)
        #pragma unroll
        for (int j = 0; j < 2; j++)
            #pragma unroll
            for (int q = 0; q < 4; q++) c[i][j][q] = 0.0f;

    // ldmatrix lane-address parts.
    const int l7  = lid & 7;
    const int lb3 = (lid >> 3) & 1;
    const int lb4 = (lid >> 4) & 1;
    const int a_row_lane = l7 + lb3 * 8;
    const int b_row_lane = l7 + lb4 * 8;
    const int nb = w_n * 16;

    auto load_stage = [&](int st, int k0) {
        const uint32_t sA = sbase + st * STAGE_BYTES;
        const uint32_t sB = sA + 8192;
        const __nv_bfloat16* ga = Ag + ld_row * INF + k0 + ld_kc * 8;
        const __nv_bfloat16* gb = Bg + ld_row * INF + k0 + ld_kc * 8;
        CP_ASYNC16(sA + soffA0, ga);
        CP_ASYNC16(sA + soffA1, ga + 32 * INF);
        CP_ASYNC16(sB + soffA0, gb);
        CP_ASYNC16(sB + soffA1, gb + 32 * INF);
    };

    load_stage(0, 0);   CP_COMMIT();
    load_stage(1, 64);  CP_COMMIT();

    for (int ch = 0; ch < 16; ch++) {
        CP_WAIT1();              // stage (ch % 3) data complete
        __syncthreads();         // safe: all reads of stage (ch+2)%3 finished (iter ch-1)
        if (ch + 2 < 16) load_stage((ch + 2) % 3, (ch + 2) * 64);
        CP_COMMIT();             // uniform group accounting (empty groups at tail)

        const uint32_t sA = sbase + (ch % 3) * STAGE_BYTES;
        const uint32_t sB = sA + 8192;

        #pragma unroll
        for (int s = 0; s < 4; s++) {
            uint32_t b0, b1, b2, b3;
            {
                const uint32_t boff = SWZ128(
                    (uint32_t)((nb + b_row_lane) * 128 + (s * 2 + lb3) * 16));
                asm volatile(
                    "ldmatrix.sync.aligned.m8n8.x4.shared.b16 {%0,%1,%2,%3}, [%4];"
                    : "=r"(b0), "=r"(b1), "=r"(b2), "=r"(b3) : "r"(sB + boff));
            }
            #pragma unroll
            for (int mf = 0; mf < 2; mf++) {
                const int mb = w_m * 32 + mf * 16;
                uint32_t a0, a1, a2, a3;
                const uint32_t aoff = SWZ128(
                    (uint32_t)((mb + a_row_lane) * 128 + (s * 2 + lb4) * 16));
                asm volatile(
                    "ldmatrix.sync.aligned.m8n8.x4.shared.b16 {%0,%1,%2,%3}, [%4];"
                    : "=r"(a0), "=r"(a1), "=r"(a2), "=r"(a3) : "r"(sA + aoff));
                asm volatile(
                    "mma.sync.aligned.m16n8k16.row.col.f32.bf16.bf16.f32 "
                    "{%0,%1,%2,%3}, {%4,%5,%6,%7}, {%8,%9}, {%0,%1,%2,%3};"
                    : "+f"(c[mf][0][0]), "+f"(c[mf][0][1]),
                      "+f"(c[mf][0][2]), "+f"(c[mf][0][3])
                    : "r"(a0), "r"(a1), "r"(a2), "r"(a3), "r"(b0), "r"(b1));
                asm volatile(
                    "mma.sync.aligned.m16n8k16.row.col.f32.bf16.bf16.f32 "
                    "{%0,%1,%2,%3}, {%4,%5,%6,%7}, {%8,%9}, {%0,%1,%2,%3};"
                    : "+f"(c[mf][1][0]), "+f"(c[mf][1][1]),
                      "+f"(c[mf][1][2]), "+f"(c[mf][1][3])
                    : "r"(a0), "r"(a1), "r"(a2), "r"(a3), "r"(b2), "r"(b3));
            }
        }
    }

    // Epilogue
    const int g = lid >> 2;
    const int tig = lid & 3;
    #pragma unroll
    for (int mf = 0; mf < 2; mf++) {
        const int row = mt * 64 + w_m * 32 + mf * 16 + g;
        #pragma unroll
        for (int nf = 0; nf < 2; nf++) {
            const int col = nt * 64 + w_n * 16 + nf * 8 + tig * 2;
            *reinterpret_cast<float2*>(&C[row * NCOLS + col]) =
                make_float2(c[mf][nf][0], c[mf][nf][1]);
            *reinterpret_cast<float2*>(&C[(row + 8) * NCOLS + col]) =
                make_float2(c[mf][nf][2], c[mf][nf][3]);
        }
    }
}

// ---------------------------------------------------------------------------
// Pairwise L1 + exp-sum, 2-way j-split.
// Grid 128 (one block per feature o), 512 threads: (i = tid&255, h = tid>>8).
// Thread (i,h) sums j in [h*128, h*128+128); halves combined via shared.
// ---------------------------------------------------------------------------
__global__ __launch_bounds__(512) void pairwise_kernel(
    const float* __restrict__ M, float* __restrict__ out)
{
    const int o = blockIdx.x;        // 0..127
    const int i = threadIdx.x & 255;
    const int h = threadIdx.x >> 8;  // 0..1

    __shared__ float4 Ms[BATCH][2];
    __shared__ float partial[BATCH];

    if (h == 0) {
        Ms[i][0] = *reinterpret_cast<const float4*>(&M[i * NCOLS + o * KD]);
        Ms[i][1] = *reinterpret_cast<const float4*>(&M[i * NCOLS + o * KD + 4]);
    }
    __syncthreads();

    const float4 a0 = Ms[i][0];
    const float4 a1 = Ms[i][1];

    float s = 0.0f;
    const int j0 = h * 128;
    #pragma unroll 4
    for (int j = j0; j < j0 + 128; j++) {
        const float4 b0 = Ms[j][0];
        const float4 b1 = Ms[j][1];
        float d = fabsf(a0.x - b0.x) + fabsf(a0.y - b0.y)
                + fabsf(a0.z - b0.z) + fabsf(a0.w - b0.w)
                + fabsf(a1.x - b1.x) + fabsf(a1.y - b1.y)
                + fabsf(a1.z - b1.z) + fabsf(a1.w - b1.w);
        s += __expf(-d);
    }

    if (h == 1) partial[i] = s;
    __syncthreads();
    if (h == 0) out[i * OUTW + INF + o] = s + partial[i] - 1.0f;
}

// ---------------------------------------------------------------------------
extern "C" void kernel_launch(void* const* d_in, const int* in_sizes, int n_in,
                              void* d_out, int out_size)
{
    const float* x = (const float*)d_in[0];   // (256, 1024)
    const float* T = (const float*)d_in[1];   // (1024, 1024)
    float* out = (float*)d_out;               // (256, 1152)

    float* M;
    __nv_bfloat16 *Abf, *Bt;
    cudaGetSymbolAddress((void**)&M, g_M);
    cudaGetSymbolAddress((void**)&Abf, g_Abf);
    cudaGetSymbolAddress((void**)&Bt, g_Bt);

    static bool attr_set = false;
    if (!attr_set) {
        cudaFuncSetAttribute(gemm_mma_kernel,
                             cudaFuncAttributeMaxDynamicSharedMemorySize, GEMM_SMEM);
        attr_set = true;
    }

    prep_x_kernel<<<(BATCH * INF / 4 + 255) / 256, 256>>>(x, out, Abf);
    transpose_T_kernel<<<dim3(NCOLS / 32, INF / 32), dim3(32, 8)>>>(T, Bt);

    gemm_mma_kernel<<<dim3(NCOLS / 64, BATCH / 64), 256, GEMM_SMEM>>>(Abf, Bt, M);

    pairwise_kernel<<<OUTF, 512>>>(M, out);
}

// round 5
// speedup vs baseline: 2.5007x; 1.0570x over previous
#include <cuda_runtime.h>
#include <cuda_bf16.h>
#include <cuda_fp16.h>
#include <cstdint>

#define BATCH 256
#define INF   1024
#define OUTF  128
#define KD    8
#define NCOLS (OUTF * KD)     // 1024
#define OUTW  (INF + OUTF)    // 1152

// Device scratch (no allocs allowed)
__device__ __align__(16) __half g_Mh[BATCH * NCOLS];   // M = x @ T, fp16
__device__ __nv_bfloat16 g_Abf[BATCH * INF];           // x in bf16 (K-major)
__device__ __nv_bfloat16 g_Bt[NCOLS * INF];            // T transposed: Bt[n][k]

__device__ __forceinline__ uint32_t smem_u32(const void* p) {
    uint32_t a;
    asm("{ .reg .u64 t; cvta.to.shared.u64 t, %1; cvt.u32.u64 %0, t; }" : "=r"(a) : "l"(p));
    return a;
}
#define SWZ128(b) ((b) ^ (((b) >> 3) & 0x70))
#define CP_ASYNC16(saddr, gptr) \
    asm volatile("cp.async.cg.shared.global [%0], [%1], 16;" :: "r"(saddr), "l"(gptr) : "memory")
#define CP_COMMIT() asm volatile("cp.async.commit_group;" ::: "memory")
#define CP_WAIT1()  asm volatile("cp.async.wait_group 1;" ::: "memory")

// ---------------------------------------------------------------------------
// Fused prep: copy x into out[:, :1024] AND convert x -> bf16 (one read).
// ---------------------------------------------------------------------------
__global__ __launch_bounds__(256) void prep_x_kernel(
    const float* __restrict__ x, float* __restrict__ out,
    __nv_bfloat16* __restrict__ xb)
{
    const int idx = blockIdx.x * blockDim.x + threadIdx.x;   // float4 index
    if (idx < BATCH * INF / 4) {
        const float4 v = reinterpret_cast<const float4*>(x)[idx];
        const int row = idx >> 8;
        const int c4  = idx & 255;
        *reinterpret_cast<float4*>(&out[row * OUTW + c4 * 4]) = v;
        reinterpret_cast<__nv_bfloat162*>(xb)[idx * 2]     = __floats2bfloat162_rn(v.x, v.y);
        reinterpret_cast<__nv_bfloat162*>(xb)[idx * 2 + 1] = __floats2bfloat162_rn(v.z, v.w);
    }
}

// ---------------------------------------------------------------------------
// Prep B: T[k][n] fp32 -> Bt[n][k] bf16 (tiled transpose)
// ---------------------------------------------------------------------------
__global__ __launch_bounds__(256) void transpose_T_kernel(
    const float* __restrict__ T, __nv_bfloat16* __restrict__ Bt)
{
    __shared__ float tile[32][33];
    const int tx = threadIdx.x;  // 0..31
    const int ty = threadIdx.y;  // 0..7
    const int n = blockIdx.x * 32 + tx;
    #pragma unroll
    for (int r = 0; r < 4; r++) {
        const int k = blockIdx.y * 32 + ty + r * 8;
        tile[ty + r * 8][tx] = T[k * NCOLS + n];
    }
    __syncthreads();
    const int k_out = blockIdx.y * 32 + tx;
    #pragma unroll
    for (int r = 0; r < 4; r++) {
        const int n_out = blockIdx.x * 32 + ty + r * 8;
        Bt[n_out * INF + k_out] = __float2bfloat16(tile[tx][ty + r * 8]);
    }
}

// ---------------------------------------------------------------------------
// HMMA GEMM, 3-stage cp.async pipeline; epilogue writes fp16 M.
// CTA tile 64x64, BK=64 (16 chunks). 8 warps = 2(m) x 4(n). Grid (16, 4).
// ---------------------------------------------------------------------------
#define STAGE_BYTES 16384
#define GEMM_SMEM   (3 * STAGE_BYTES)

__global__ __launch_bounds__(256) void gemm_mma_kernel(
    const __nv_bfloat16* __restrict__ A, const __nv_bfloat16* __restrict__ B,
    __half* __restrict__ C)
{
    extern __shared__ __align__(1024) char dsm[];

    const int tid = threadIdx.x;
    const int wid = tid >> 5;
    const int lid = tid & 31;
    const int nt = blockIdx.x;
    const int mt = blockIdx.y;
    const int w_m = wid >> 2;
    const int w_n = wid & 3;

    const uint32_t sbase = smem_u32(dsm);

    const __nv_bfloat16* Ag = A + (size_t)(mt * 64) * INF;
    const __nv_bfloat16* Bg = B + (size_t)(nt * 64) * INF;

    const int ld_row  = tid >> 3;
    const int ld_kc   = tid & 7;
    const uint32_t soffA0 = SWZ128((uint32_t)(ld_row * 128 + ld_kc * 16));
    const uint32_t soffA1 = SWZ128((uint32_t)((ld_row + 32) * 128 + ld_kc * 16));

    float c[2][2][4];
    #pragma unroll
    for (int i = 0; i < 2; i++)
        #pragma unroll
        for (int j = 0; j < 2; j++)
            #pragma unroll
            for (int q = 0; q < 4; q++) c[i][j][q] = 0.0f;

    const int l7  = lid & 7;
    const int lb3 = (lid >> 3) & 1;
    const int lb4 = (lid >> 4) & 1;
    const int a_row_lane = l7 + lb3 * 8;
    const int b_row_lane = l7 + lb4 * 8;
    const int nb = w_n * 16;

    auto load_stage = [&](int st, int k0) {
        const uint32_t sA = sbase + st * STAGE_BYTES;
        const uint32_t sB = sA + 8192;
        const __nv_bfloat16* ga = Ag + ld_row * INF + k0 + ld_kc * 8;
        const __nv_bfloat16* gb = Bg + ld_row * INF + k0 + ld_kc * 8;
        CP_ASYNC16(sA + soffA0, ga);
        CP_ASYNC16(sA + soffA1, ga + 32 * INF);
        CP_ASYNC16(sB + soffA0, gb);
        CP_ASYNC16(sB + soffA1, gb + 32 * INF);
    };

    load_stage(0, 0);   CP_COMMIT();
    load_stage(1, 64);  CP_COMMIT();

    for (int ch = 0; ch < 16; ch++) {
        CP_WAIT1();
        __syncthreads();
        if (ch + 2 < 16) load_stage((ch + 2) % 3, (ch + 2) * 64);
        CP_COMMIT();

        const uint32_t sA = sbase + (ch % 3) * STAGE_BYTES;
        const uint32_t sB = sA + 8192;

        #pragma unroll
        for (int s = 0; s < 4; s++) {
            uint32_t b0, b1, b2, b3;
            {
                const uint32_t boff = SWZ128(
                    (uint32_t)((nb + b_row_lane) * 128 + (s * 2 + lb3) * 16));
                asm volatile(
                    "ldmatrix.sync.aligned.m8n8.x4.shared.b16 {%0,%1,%2,%3}, [%4];"
                    : "=r"(b0), "=r"(b1), "=r"(b2), "=r"(b3) : "r"(sB + boff));
            }
            #pragma unroll
            for (int mf = 0; mf < 2; mf++) {
                const int mb = w_m * 32 + mf * 16;
                uint32_t a0, a1, a2, a3;
                const uint32_t aoff = SWZ128(
                    (uint32_t)((mb + a_row_lane) * 128 + (s * 2 + lb4) * 16));
                asm volatile(
                    "ldmatrix.sync.aligned.m8n8.x4.shared.b16 {%0,%1,%2,%3}, [%4];"
                    : "=r"(a0), "=r"(a1), "=r"(a2), "=r"(a3) : "r"(sA + aoff));
                asm volatile(
                    "mma.sync.aligned.m16n8k16.row.col.f32.bf16.bf16.f32 "
                    "{%0,%1,%2,%3}, {%4,%5,%6,%7}, {%8,%9}, {%0,%1,%2,%3};"
                    : "+f"(c[mf][0][0]), "+f"(c[mf][0][1]),
                      "+f"(c[mf][0][2]), "+f"(c[mf][0][3])
                    : "r"(a0), "r"(a1), "r"(a2), "r"(a3), "r"(b0), "r"(b1));
                asm volatile(
                    "mma.sync.aligned.m16n8k16.row.col.f32.bf16.bf16.f32 "
                    "{%0,%1,%2,%3}, {%4,%5,%6,%7}, {%8,%9}, {%0,%1,%2,%3};"
                    : "+f"(c[mf][1][0]), "+f"(c[mf][1][1]),
                      "+f"(c[mf][1][2]), "+f"(c[mf][1][3])
                    : "r"(a0), "r"(a1), "r"(a2), "r"(a3), "r"(b2), "r"(b3));
            }
        }
    }

    // Epilogue: write fp16 (half2 pairs)
    const int g = lid >> 2;
    const int tig = lid & 3;
    #pragma unroll
    for (int mf = 0; mf < 2; mf++) {
        const int row = mt * 64 + w_m * 32 + mf * 16 + g;
        #pragma unroll
        for (int nf = 0; nf < 2; nf++) {
            const int col = nt * 64 + w_n * 16 + nf * 8 + tig * 2;
            *reinterpret_cast<__half2*>(&C[row * NCOLS + col]) =
                __floats2half2_rn(c[mf][nf][0], c[mf][nf][1]);
            *reinterpret_cast<__half2*>(&C[(row + 8) * NCOLS + col]) =
                __floats2half2_rn(c[mf][nf][2], c[mf][nf][3]);
        }
    }
}

// ---------------------------------------------------------------------------
// Pairwise L1 + exp-sum, fp16x2.
// Grid 256 = (o, i-half). 512 threads = 128 i-local x 4-way j-split (64 j).
// Shared: all 256 samples' 8 halfs for feature o (4 KB).
// ---------------------------------------------------------------------------
__global__ __launch_bounds__(512) void pairwise_kernel(
    const __half* __restrict__ Mh, float* __restrict__ out)
{
    const int o  = blockIdx.x >> 1;       // 0..127
    const int ih = blockIdx.x & 1;        // 0..1
    const int il = threadIdx.x & 127;     // 0..127
    const int h  = threadIdx.x >> 7;      // 0..3
    const int i  = ih * 128 + il;

    __shared__ uint4 Ms[BATCH];
    __shared__ float psum[3][128];

    if (threadIdx.x < BATCH)
        Ms[threadIdx.x] = *reinterpret_cast<const uint4*>(
            &Mh[threadIdx.x * NCOLS + o * KD]);
    __syncthreads();

    uint4 av = Ms[i];
    const __half2 a0 = *reinterpret_cast<__half2*>(&av.x);
    const __half2 a1 = *reinterpret_cast<__half2*>(&av.y);
    const __half2 a2 = *reinterpret_cast<__half2*>(&av.z);
    const __half2 a3 = *reinterpret_cast<__half2*>(&av.w);

    float s = 0.0f;
    const int j0 = h * 64;
    #pragma unroll 4
    for (int j = j0; j < j0 + 64; j++) {
        uint4 bv = Ms[j];   // uniform j -> LDS broadcast
        const __half2 d0 = __habs2(__hsub2(a0, *reinterpret_cast<__half2*>(&bv.x)));
        const __half2 d1 = __habs2(__hsub2(a1, *reinterpret_cast<__half2*>(&bv.y)));
        const __half2 d2 = __habs2(__hsub2(a2, *reinterpret_cast<__half2*>(&bv.z)));
        const __half2 d3 = __habs2(__hsub2(a3, *reinterpret_cast<__half2*>(&bv.w)));
        const __half2 t = __hadd2(__hadd2(d0, d1), __hadd2(d2, d3));
        const float dsum = __low2float(t) + __high2float(t);
        s += __expf(-dsum);
    }

    if (h) psum[h - 1][il] = s;
    __syncthreads();
    if (h == 0)
        out[i * OUTW + INF + o] = s + psum[0][il] + psum[1][il] + psum[2][il] - 1.0f;
}

// ---------------------------------------------------------------------------
extern "C" void kernel_launch(void* const* d_in, const int* in_sizes, int n_in,
                              void* d_out, int out_size)
{
    const float* x = (const float*)d_in[0];   // (256, 1024)
    const float* T = (const float*)d_in[1];   // (1024, 1024)
    float* out = (float*)d_out;               // (256, 1152)

    __half* Mh;
    __nv_bfloat16 *Abf, *Bt;
    cudaGetSymbolAddress((void**)&Mh, g_Mh);
    cudaGetSymbolAddress((void**)&Abf, g_Abf);
    cudaGetSymbolAddress((void**)&Bt, g_Bt);

    static bool attr_set = false;
    if (!attr_set) {
        cudaFuncSetAttribute(gemm_mma_kernel,
                             cudaFuncAttributeMaxDynamicSharedMemorySize, GEMM_SMEM);
        attr_set = true;
    }

    prep_x_kernel<<<(BATCH * INF / 4 + 255) / 256, 256>>>(x, out, Abf);
    transpose_T_kernel<<<dim3(NCOLS / 32, INF / 32), dim3(32, 8)>>>(T, Bt);

    gemm_mma_kernel<<<dim3(NCOLS / 64, BATCH / 64), 256, GEMM_SMEM>>>(Abf, Bt, Mh);

    pairwise_kernel<<<2 * OUTF, 512>>>(Mh, out);
}

// round 6
// speedup vs baseline: 2.7409x; 1.0960x over previous
#include <cuda_runtime.h>
#include <cuda_bf16.h>
#include <cuda_fp16.h>
#include <cstdint>

#define BATCH 256
#define INF   1024
#define OUTF  128
#define KD    8
#define NCOLS (OUTF * KD)     // 1024
#define OUTW  (INF + OUTF)    // 1152

// Device scratch (no allocs allowed)
__device__ __align__(16) __half g_Mh[BATCH * NCOLS];   // M = x @ T, fp16
__device__ __nv_bfloat16 g_Abf[BATCH * INF];           // x in bf16 (K-major)
__device__ __nv_bfloat16 g_Bt[NCOLS * INF];            // T transposed: Bt[n][k]

__device__ __forceinline__ uint32_t smem_u32(const void* p) {
    uint32_t a;
    asm("{ .reg .u64 t; cvta.to.shared.u64 t, %1; cvt.u32.u64 %0, t; }" : "=r"(a) : "l"(p));
    return a;
}
#define SWZ128(b) ((b) ^ (((b) >> 3) & 0x70))
#define CP_ASYNC16(saddr, gptr) \
    asm volatile("cp.async.cg.shared.global [%0], [%1], 16;" :: "r"(saddr), "l"(gptr) : "memory")
#define CP_COMMIT() asm volatile("cp.async.commit_group;" ::: "memory")
#define CP_WAIT1()  asm volatile("cp.async.wait_group 1;" ::: "memory")

// ---------------------------------------------------------------------------
// Fused prep: copy x into out[:, :1024] AND convert x -> bf16 (one read).
// ---------------------------------------------------------------------------
__global__ __launch_bounds__(256) void prep_x_kernel(
    const float* __restrict__ x, float* __restrict__ out,
    __nv_bfloat16* __restrict__ xb)
{
    const int idx = blockIdx.x * blockDim.x + threadIdx.x;   // float4 index
    if (idx < BATCH * INF / 4) {
        const float4 v = reinterpret_cast<const float4*>(x)[idx];
        const int row = idx >> 8;
        const int c4  = idx & 255;
        *reinterpret_cast<float4*>(&out[row * OUTW + c4 * 4]) = v;
        reinterpret_cast<__nv_bfloat162*>(xb)[idx * 2]     = __floats2bfloat162_rn(v.x, v.y);
        reinterpret_cast<__nv_bfloat162*>(xb)[idx * 2 + 1] = __floats2bfloat162_rn(v.z, v.w);
    }
}

// ---------------------------------------------------------------------------
// Prep B: T[k][n] fp32 -> Bt[n][k] bf16 (tiled transpose)
// ---------------------------------------------------------------------------
__global__ __launch_bounds__(256) void transpose_T_kernel(
    const float* __restrict__ T, __nv_bfloat16* __restrict__ Bt)
{
    __shared__ float tile[32][33];
    const int tx = threadIdx.x;  // 0..31
    const int ty = threadIdx.y;  // 0..7
    const int n = blockIdx.x * 32 + tx;
    #pragma unroll
    for (int r = 0; r < 4; r++) {
        const int k = blockIdx.y * 32 + ty + r * 8;
        tile[ty + r * 8][tx] = T[k * NCOLS + n];
    }
    __syncthreads();
    const int k_out = blockIdx.y * 32 + tx;
    #pragma unroll
    for (int r = 0; r < 4; r++) {
        const int n_out = blockIdx.x * 32 + ty + r * 8;
        Bt[n_out * INF + k_out] = __float2bfloat16(tile[tx][ty + r * 8]);
    }
}

// ---------------------------------------------------------------------------
// HMMA GEMM, 3-stage cp.async pipeline; epilogue writes fp16 M.
// CTA tile M=32 x N=64, BK=64 (16 chunks). 8 warps = 2(m) x 4(n);
// warp tile 16x16. Grid (16 nt, 8 mt) = 128 CTAs.
// smem: 3 stages x (A 4KB + B 8KB) = 36KB.
// ---------------------------------------------------------------------------
#define STAGE_BYTES 12288
#define GEMM_SMEM   (3 * STAGE_BYTES)

__global__ __launch_bounds__(256) void gemm_mma_kernel(
    const __nv_bfloat16* __restrict__ A, const __nv_bfloat16* __restrict__ B,
    __half* __restrict__ C)
{
    extern __shared__ __align__(1024) char dsm[];

    const int tid = threadIdx.x;
    const int wid = tid >> 5;
    const int lid = tid & 31;
    const int nt = blockIdx.x;   // 0..15
    const int mt = blockIdx.y;   // 0..7
    const int w_m = wid >> 2;    // 0..1
    const int w_n = wid & 3;     // 0..3

    const uint32_t sbase = smem_u32(dsm);

    const __nv_bfloat16* Ag = A + (size_t)(mt * 32) * INF;
    const __nv_bfloat16* Bg = B + (size_t)(nt * 64) * INF;

    const int ld_row  = tid >> 3;          // 0..31
    const int ld_kc   = tid & 7;           // 0..7
    const uint32_t soff0 = SWZ128((uint32_t)(ld_row * 128 + ld_kc * 16));
    const uint32_t soff1 = SWZ128((uint32_t)((ld_row + 32) * 128 + ld_kc * 16));

    float c[2][4];
    #pragma unroll
    for (int j = 0; j < 2; j++)
        #pragma unroll
        for (int q = 0; q < 4; q++) c[j][q] = 0.0f;

    const int l7  = lid & 7;
    const int lb3 = (lid >> 3) & 1;
    const int lb4 = (lid >> 4) & 1;
    const int a_row_lane = l7 + lb3 * 8;
    const int b_row_lane = l7 + lb4 * 8;
    const int nb = w_n * 16;
    const int mb = w_m * 16;

    auto load_stage = [&](int st, int k0) {
        const uint32_t sA = sbase + st * STAGE_BYTES;
        const uint32_t sB = sA + 4096;
        const __nv_bfloat16* ga = Ag + ld_row * INF + k0 + ld_kc * 8;
        const __nv_bfloat16* gb = Bg + ld_row * INF + k0 + ld_kc * 8;
        CP_ASYNC16(sA + soff0, ga);                 // A: 32 rows, 1 unit/thread
        CP_ASYNC16(sB + soff0, gb);                 // B: 64 rows, 2 units/thread
        CP_ASYNC16(sB + soff1, gb + 32 * INF);
    };

    load_stage(0, 0);   CP_COMMIT();
    load_stage(1, 64);  CP_COMMIT();

    for (int ch = 0; ch < 16; ch++) {
        CP_WAIT1();
        __syncthreads();
        if (ch + 2 < 16) load_stage((ch + 2) % 3, (ch + 2) * 64);
        CP_COMMIT();

        const uint32_t sA = sbase + (ch % 3) * STAGE_BYTES;
        const uint32_t sB = sA + 4096;

        #pragma unroll
        for (int s = 0; s < 4; s++) {
            uint32_t b0, b1, b2, b3;
            {
                const uint32_t boff = SWZ128(
                    (uint32_t)((nb + b_row_lane) * 128 + (s * 2 + lb3) * 16));
                asm volatile(
                    "ldmatrix.sync.aligned.m8n8.x4.shared.b16 {%0,%1,%2,%3}, [%4];"
                    : "=r"(b0), "=r"(b1), "=r"(b2), "=r"(b3) : "r"(sB + boff));
            }
            uint32_t a0, a1, a2, a3;
            {
                const uint32_t aoff = SWZ128(
                    (uint32_t)((mb + a_row_lane) * 128 + (s * 2 + lb4) * 16));
                asm volatile(
                    "ldmatrix.sync.aligned.m8n8.x4.shared.b16 {%0,%1,%2,%3}, [%4];"
                    : "=r"(a0), "=r"(a1), "=r"(a2), "=r"(a3) : "r"(sA + aoff));
            }
            asm volatile(
                "mma.sync.aligned.m16n8k16.row.col.f32.bf16.bf16.f32 "
                "{%0,%1,%2,%3}, {%4,%5,%6,%7}, {%8,%9}, {%0,%1,%2,%3};"
                : "+f"(c[0][0]), "+f"(c[0][1]), "+f"(c[0][2]), "+f"(c[0][3])
                : "r"(a0), "r"(a1), "r"(a2), "r"(a3), "r"(b0), "r"(b1));
            asm volatile(
                "mma.sync.aligned.m16n8k16.row.col.f32.bf16.bf16.f32 "
                "{%0,%1,%2,%3}, {%4,%5,%6,%7}, {%8,%9}, {%0,%1,%2,%3};"
                : "+f"(c[1][0]), "+f"(c[1][1]), "+f"(c[1][2]), "+f"(c[1][3])
                : "r"(a0), "r"(a1), "r"(a2), "r"(a3), "r"(b2), "r"(b3));
        }
    }

    // Epilogue: write fp16 (half2 pairs)
    const int g = lid >> 2;
    const int tig = lid & 3;
    const int row = mt * 32 + mb + g;
    #pragma unroll
    for (int nf = 0; nf < 2; nf++) {
        const int col = nt * 64 + nb + nf * 8 + tig * 2;
        *reinterpret_cast<__half2*>(&C[row * NCOLS + col]) =
            __floats2half2_rn(c[nf][0], c[nf][1]);
        *reinterpret_cast<__half2*>(&C[(row + 8) * NCOLS + col]) =
            __floats2half2_rn(c[nf][2], c[nf][3]);
    }
}

// ---------------------------------------------------------------------------
// Pairwise L1 + exp-sum, fp16x2.
// Grid 512 = (o, i-quarter). 512 threads = 64 i-local x 8-way j-split (32 j).
// ---------------------------------------------------------------------------
__global__ __launch_bounds__(512) void pairwise_kernel(
    const __half* __restrict__ Mh, float* __restrict__ out)
{
    const int o  = blockIdx.x >> 2;       // 0..127
    const int iq = blockIdx.x & 3;        // 0..3
    const int il = threadIdx.x & 63;      // 0..63
    const int h  = threadIdx.x >> 6;      // 0..7
    const int i  = iq * 64 + il;

    __shared__ uint4 Ms[BATCH];
    __shared__ float psum[7][64];

    if (threadIdx.x < BATCH)
        Ms[threadIdx.x] = *reinterpret_cast<const uint4*>(
            &Mh[threadIdx.x * NCOLS + o * KD]);
    __syncthreads();

    uint4 av = Ms[i];
    const __half2 a0 = *reinterpret_cast<__half2*>(&av.x);
    const __half2 a1 = *reinterpret_cast<__half2*>(&av.y);
    const __half2 a2 = *reinterpret_cast<__half2*>(&av.z);
    const __half2 a3 = *reinterpret_cast<__half2*>(&av.w);

    float s = 0.0f;
    const int j0 = h * 32;
    #pragma unroll 8
    for (int j = j0; j < j0 + 32; j++) {
        uint4 bv = Ms[j];   // uniform j -> LDS broadcast
        const __half2 d0 = __habs2(__hsub2(a0, *reinterpret_cast<__half2*>(&bv.x)));
        const __half2 d1 = __habs2(__hsub2(a1, *reinterpret_cast<__half2*>(&bv.y)));
        const __half2 d2 = __habs2(__hsub2(a2, *reinterpret_cast<__half2*>(&bv.z)));
        const __half2 d3 = __habs2(__hsub2(a3, *reinterpret_cast<__half2*>(&bv.w)));
        const __half2 t = __hadd2(__hadd2(d0, d1), __hadd2(d2, d3));
        const float dsum = __low2float(t) + __high2float(t);
        s += __expf(-dsum);
    }

    if (h) psum[h - 1][il] = s;
    __syncthreads();
    if (h == 0) {
        float tot = s - 1.0f;
        #pragma unroll
        for (int q = 0; q < 7; q++) tot += psum[q][il];
        out[i * OUTW + INF + o] = tot;
    }
}

// ---------------------------------------------------------------------------
extern "C" void kernel_launch(void* const* d_in, const int* in_sizes, int n_in,
                              void* d_out, int out_size)
{
    const float* x = (const float*)d_in[0];   // (256, 1024)
    const float* T = (const float*)d_in[1];   // (1024, 1024)
    float* out = (float*)d_out;               // (256, 1152)

    __half* Mh;
    __nv_bfloat16 *Abf, *Bt;
    cudaGetSymbolAddress((void**)&Mh, g_Mh);
    cudaGetSymbolAddress((void**)&Abf, g_Abf);
    cudaGetSymbolAddress((void**)&Bt, g_Bt);

    static bool attr_set = false;
    if (!attr_set) {
        cudaFuncSetAttribute(gemm_mma_kernel,
                             cudaFuncAttributeMaxDynamicSharedMemorySize, GEMM_SMEM);
        attr_set = true;
    }

    prep_x_kernel<<<(BATCH * INF / 4 + 255) / 256, 256>>>(x, out, Abf);
    transpose_T_kernel<<<dim3(NCOLS / 32, INF / 32), dim3(32, 8)>>>(T, Bt);

    gemm_mma_kernel<<<dim3(NCOLS / 64, BATCH / 32), 256, GEMM_SMEM>>>(Abf, Bt, Mh);

    pairwise_kernel<<<4 * OUTF, 512>>>(Mh, out);
}